// round 14
// baseline (speedup 1.0000x reference)
#include <cuda_runtime.h>
#include <cuda_fp16.h>
#include <cstring>
#include <cstdint>

#define NN 50000
#define EE 400000
#define NHEAD 8
#define DEF 16
#define DNF 16

// ---------------- device global scratch ------------------------------------
__device__ float g_wsum[DEF];
// B operands as fp16 [n][k], row stride 136 (slot 0:tsrc 1:edge 2:tdst 3:hnode)
__device__ __half g_Bh[4 * 128 * 136];
__device__ __half g_tsrc[NN * 128];
__device__ __half g_tdst[NN * 128];
__device__ __half g_hnode[NN * 128];
__device__ float g_a[EE * NHEAD];    // exp(logit) * norm
__device__ float g_den[NN * NHEAD];  // sum of raw exp(logit)

// ---------------- smem layouts (bytes) ---------------------------------------
#define RSTRIDE 272                 // 136 fp16 per row
#define AB_BYTES (128 * RSTRIDE)    // 34816

// edge kernel: bias | ws | A | B | pd  (no fbuf; fragment epilogue)
#define SM_BIAS 0
#define SM_WS   512
#define SM_A    1024
#define SM_BHI  (SM_A + AB_BYTES)       // 35840
#define SM_PD   (SM_BHI + AB_BYTES)     // 70656
#define SM_TOTAL (SM_PD + 128 * 16 * 4) // 78848  (2 CTAs/SM, big L1 left)

// fused node kernel layout
#define SMN_BIAS 0
#define SMN_AHI  1024
#define SMN_B0   (SMN_AHI + AB_BYTES)           // 35840
#define SMN_TOTAL (SMN_B0 + 3 * AB_BYTES)       // 140288

// ---------------- helpers ------------------------------------------------------
__device__ __forceinline__ uint32_t smem_u32(const void* p) {
    uint32_t a;
    asm("{ .reg .u64 t; cvta.to.shared.u64 t, %1; cvt.u32.u64 %0, t; }" : "=r"(a) : "l"(p));
    return a;
}
__device__ __forceinline__ float2 h2f2(uint32_t u) {
    __half2 h;
    memcpy(&h, &u, 4);
    return __half22float2(h);
}
// 256-bit streaming load (this toolchain requires v8.b32 for L2::evict_first)
__device__ __forceinline__ void ldg_stream8(const float* p, float4& v0, float4& v1) {
    uint32_t r0, r1, r2, r3, r4, r5, r6, r7;
    asm volatile("ld.global.nc.L2::evict_first.v8.b32 {%0,%1,%2,%3,%4,%5,%6,%7}, [%8];"
                 : "=r"(r0), "=r"(r1), "=r"(r2), "=r"(r3),
                   "=r"(r4), "=r"(r5), "=r"(r6), "=r"(r7) : "l"(p));
    v0.x = __uint_as_float(r0); v0.y = __uint_as_float(r1);
    v0.z = __uint_as_float(r2); v0.w = __uint_as_float(r3);
    v1.x = __uint_as_float(r4); v1.y = __uint_as_float(r5);
    v1.z = __uint_as_float(r6); v1.w = __uint_as_float(r7);
}
__device__ __forceinline__ void stg_stream8(float* p, const float* v) {
    asm volatile("st.global.L2::evict_first.v8.b32 [%0], {%1,%2,%3,%4,%5,%6,%7,%8};"
                 :: "l"(p),
                    "r"(__float_as_uint(v[0])), "r"(__float_as_uint(v[1])),
                    "r"(__float_as_uint(v[2])), "r"(__float_as_uint(v[3])),
                    "r"(__float_as_uint(v[4])), "r"(__float_as_uint(v[5])),
                    "r"(__float_as_uint(v[6])), "r"(__float_as_uint(v[7])));
}
__device__ __forceinline__ void pf_l2(const void* p) {
    asm volatile("prefetch.global.L2 [%0];" :: "l"(p));
}

// ---------------- small kernels ----------------------------------------------
__global__ void k_init(float* __restrict__ out1) {
    int i = blockIdx.x * blockDim.x + threadIdx.x;
    if (i < NN * NHEAD) g_den[i] = 0.f;
    if (i < NN * DNF)   out1[i] = 0.f;
}

// fused: combined weights -> fp16 B operands directly
__global__ void k_wb(const float* __restrict__ W_edges,
                     const float* __restrict__ W_ni,
                     const float* __restrict__ W_nj,
                     const float* __restrict__ W_fij,
                     const float* __restrict__ W_node,
                     const float* __restrict__ W_attn) {
    int k = blockIdx.x, c = threadIdx.x, m = blockIdx.y;
    float acc = 0.f;
    if (m == 0) {
        for (int j = 0; j < 128; ++j) acc += W_edges[c * 384 + j] * W_ni[j * 128 + k];
    } else if (m == 1) {
        for (int j = 0; j < 128; ++j) acc += W_edges[c * 384 + 128 + j] * W_fij[j * 128 + k];
    } else if (m == 2) {
        for (int j = 0; j < 128; ++j) acc += W_edges[c * 384 + 256 + j] * W_nj[j * 128 + k];
    } else {
        acc = W_node[c * 128 + k];
        if (k == 0 && c < DEF) {
            float s = 0.f;
            for (int h = 0; h < NHEAD; ++h) s += W_attn[h * DEF + c];
            g_wsum[c] = s;
        }
    }
    g_Bh[m * 128 * 136 + c * 136 + k] = __float2half_rn(acc);
}

// ---------------- fp32 -> fp16 tile stage -------------------------------------
__device__ __forceinline__ uint4 cvt8(const float4 v0, const float4 v1) {
    unsigned hu[4];
    __half2 h0 = __floats2half2_rn(v0.x, v0.y);
    __half2 h1 = __floats2half2_rn(v0.z, v0.w);
    __half2 h2 = __floats2half2_rn(v1.x, v1.y);
    __half2 h3 = __floats2half2_rn(v1.z, v1.w);
    memcpy(&hu[0], &h0, 4);
    memcpy(&hu[1], &h1, 4);
    memcpy(&hu[2], &h2, 4);
    memcpy(&hu[3], &h3, 4);
    return make_uint4(hu[0], hu[1], hu[2], hu[3]);
}

// node variant: normal loads (nfeats re-used across 3 mats in-kernel)
__device__ __forceinline__ void load_tile(char* smc, int ahioff,
                                          const float* __restrict__ srcp,
                                          int base, int limit, int t) {
    for (int i = t; i < 2048; i += 256) {
        int row = i >> 4, col = (i & 15) * 8;
        int gr = base + row;
        float4 v0, v1;
        if (gr < limit) {
            v0 = __ldg((const float4*)(srcp + (size_t)gr * 128 + col));
            v1 = __ldg((const float4*)(srcp + (size_t)gr * 128 + col + 4));
        } else {
            v0 = make_float4(0.f, 0.f, 0.f, 0.f); v1 = v0;
        }
        *(uint4*)(smc + ahioff + row * RSTRIDE + col * 2) = cvt8(v0, v1);
    }
}

// edge variant: 256-bit streaming evict_first loads (protect gather tables in L2)
__device__ __forceinline__ void load_tile_stream(char* smc, int ahioff,
                                                 const float* __restrict__ srcp,
                                                 int base, int t) {
    for (int i = t; i < 2048; i += 256) {
        int row = i >> 4, col = (i & 15) * 8;
        int gr = base + row;
        float4 v0, v1;
        ldg_stream8(srcp + (size_t)gr * 128 + col, v0, v1);
        *(uint4*)(smc + ahioff + row * RSTRIDE + col * 2) = cvt8(v0, v1);
    }
}

// ---------------- mma core (ldmatrix + single fp16 pass) -----------------------
__device__ __forceinline__ void mma16816(float (&d)[4], const uint32_t (&a)[4],
                                         uint32_t b0, uint32_t b1) {
    asm("mma.sync.aligned.m16n8k16.row.col.f32.f16.f16.f32 "
        "{%0,%1,%2,%3}, {%4,%5,%6,%7}, {%8,%9}, {%0,%1,%2,%3};"
        : "+f"(d[0]), "+f"(d[1]), "+f"(d[2]), "+f"(d[3])
        : "r"(a[0]), "r"(a[1]), "r"(a[2]), "r"(a[3]), "r"(b0), "r"(b1));
}

__device__ __forceinline__ void ldmat4(uint32_t (&r)[4], uint32_t addr) {
    asm volatile("ldmatrix.sync.aligned.m8n8.x4.shared.b16 {%0,%1,%2,%3}, [%4];"
                 : "=r"(r[0]), "=r"(r[1]), "=r"(r[2]), "=r"(r[3]) : "r"(addr));
}

// block tile 128x128, warp tile 64x32
__device__ __forceinline__ void mm_one(uint32_t aBase, uint32_t bBase,
                                       int warp, int lane, float (&acc)[4][4][4]) {
    int warpm = warp & 1, warpn = warp >> 1;
    uint32_t a_addr = aBase + (uint32_t)((warpm * 64 + (lane & 15)) * RSTRIDE + ((lane >> 4) << 4));
    uint32_t b_addr = bBase + (uint32_t)((warpn * 32 + (lane & 7) + ((lane >> 4) << 3)) * RSTRIDE
                                         + (((lane >> 3) & 1) << 4));

#pragma unroll
    for (int mt = 0; mt < 4; ++mt)
#pragma unroll
        for (int nt = 0; nt < 4; ++nt)
#pragma unroll
            for (int j = 0; j < 4; ++j) acc[mt][nt][j] = 0.f;

#pragma unroll
    for (int k0 = 0; k0 < 8; ++k0) {
        uint32_t ko = k0 * 32;
        uint32_t ahi[4][4], bhi[2][4];
#pragma unroll
        for (int mt = 0; mt < 4; ++mt)
            ldmat4(ahi[mt], a_addr + mt * 16 * RSTRIDE + ko);
#pragma unroll
        for (int g = 0; g < 2; ++g)
            ldmat4(bhi[g], b_addr + g * 16 * RSTRIDE + ko);
#pragma unroll
        for (int mt = 0; mt < 4; ++mt)
#pragma unroll
            for (int nt = 0; nt < 4; ++nt)
                mma16816(acc[mt][nt], ahi[mt],
                         bhi[nt >> 1][(nt & 1) * 2], bhi[nt >> 1][(nt & 1) * 2 + 1]);
    }
}

// ---------------- fused node GEMMs: t_src / t_dst / h_node --------------------
__global__ void __launch_bounds__(256, 1)
k_node_mma(const float* __restrict__ nfeats, const float* __restrict__ b_node) {
    extern __shared__ char smc[];
    uint32_t sbase = smem_u32(smc);
    int t = threadIdx.x, warp = t >> 5, lane = t & 31;
    int warpm = warp & 1, warpn = warp >> 1;
    int q = lane >> 2, tid = lane & 3;

    // stage the 3 B operands (slots 0: tsrc, 2: tdst, 3: hnode)
    for (int i = t; i < 2176; i += 256) {
        ((uint4*)(smc + SMN_B0))[i]                = ((const uint4*)(g_Bh + 0 * 128 * 136))[i];
        ((uint4*)(smc + SMN_B0 + AB_BYTES))[i]     = ((const uint4*)(g_Bh + 2 * 128 * 136))[i];
        ((uint4*)(smc + SMN_B0 + 2 * AB_BYTES))[i] = ((const uint4*)(g_Bh + 3 * 128 * 136))[i];
    }
    float* bias_s = (float*)(smc + SMN_BIAS);
    for (int i = t; i < 128; i += 256) bias_s[i] = __ldg(&b_node[i]);

    const int ntiles = (NN + 127) / 128;   // 391
    for (int tile = blockIdx.x; tile < ntiles; tile += gridDim.x) {
        int n0 = tile * 128;
        load_tile(smc, SMN_AHI, nfeats, n0, NN, t);
        __syncthreads();
#pragma unroll 1
        for (int mat = 0; mat < 3; ++mat) {
            __half* OUT = (mat == 0) ? g_tsrc : (mat == 1 ? g_tdst : g_hnode);
            float acc[4][4][4];
            mm_one(sbase + SMN_AHI, sbase + SMN_B0 + mat * AB_BYTES, warp, lane, acc);
            // direct fragment -> fp16 gmem store
#pragma unroll
            for (int mt = 0; mt < 4; ++mt) {
                int rr = warpm * 64 + mt * 16 + q;
#pragma unroll
                for (int nt = 0; nt < 4; ++nt) {
                    int cc = warpn * 32 + nt * 8 + 2 * tid;
                    float b0 = 0.f, b1 = 0.f;
                    if (mat == 2) { b0 = bias_s[cc]; b1 = bias_s[cc + 1]; }
                    int n1 = n0 + rr, n2 = n1 + 8;
                    if (n1 < NN)
                        *(__half2*)(OUT + (size_t)n1 * 128 + cc) =
                            __floats2half2_rn(acc[mt][nt][0] + b0, acc[mt][nt][1] + b1);
                    if (n2 < NN)
                        *(__half2*)(OUT + (size_t)n2 * 128 + cc) =
                            __floats2half2_rn(acc[mt][nt][2] + b0, acc[mt][nt][3] + b1);
                }
            }
        }
        __syncthreads();   // all reads of A done before next load_tile
    }
}

// ---------------- fused edge kernel (fragment epilogue, 2 barriers/tile) -------
__global__ void __launch_bounds__(256, 2)
k_edge_mma(const float* __restrict__ efeats, const int* __restrict__ src,
           const int* __restrict__ dst, const float* __restrict__ norm,
           const float* __restrict__ bias, float* __restrict__ out2) {
    extern __shared__ char smc[];
    uint32_t sbase = smem_u32(smc);
    int t = threadIdx.x, warp = t >> 5, lane = t & 31;
    int warpm = warp & 1, warpn = warp >> 1;
    int q = lane >> 2, tid = lane & 3;

    const uint4* bh = (const uint4*)(g_Bh + 1 * 128 * 136);
    for (int i = t; i < 2176; i += 256)
        ((uint4*)(smc + SM_BHI))[i] = bh[i];
    float* bias_s = (float*)(smc + SM_BIAS);
    float* ws_s   = (float*)(smc + SM_WS);
    float* pd_s   = (float*)(smc + SM_PD);
    for (int i = t; i < 128; i += 256) bias_s[i] = __ldg(&bias[i]);
    if (t < DEF) ws_s[t] = g_wsum[t];
    // zero pd buffer
    for (int i = t; i < 128 * 16 / 4; i += 256)
        ((float4*)pd_s)[i] = make_float4(0.f, 0.f, 0.f, 0.f);

    const int ntiles = EE / 128;   // 3125 exact
    int tile = blockIdx.x;
    // prologue: stage first tile (grid 296 << 3125, always valid)
    load_tile_stream(smc, SM_A, efeats, tile * 128, t);
    __syncthreads();

    // per-thread constants for the fragment epilogue
    float wsv[4] = {ws_s[2 * tid], ws_s[2 * tid + 1], ws_s[8 + 2 * tid], ws_s[8 + 2 * tid + 1]};
    float bv[8];
#pragma unroll
    for (int nt = 0; nt < 4; ++nt) {
        bv[nt * 2]     = bias_s[warpn * 32 + nt * 8 + 2 * tid];
        bv[nt * 2 + 1] = bias_s[warpn * 32 + nt * 8 + 2 * tid + 1];
    }

    for (; tile < ntiles; tile += gridDim.x) {
        int e0 = tile * 128;
        // L2 prefetch two strides ahead
        int nxt2 = tile + 2 * (int)gridDim.x;
        if (nxt2 < ntiles) {
            const char* nb = (const char*)(efeats + (size_t)nxt2 * 128 * 128);
            pf_l2(nb + t * 256);
            pf_l2(nb + t * 256 + 128);
        }
        // gather-row L2 prefetch for this tile (lead ~ mma duration)
        {
            int ep = e0 + (t >> 1);
            int sp = __ldg(&src[ep]);
            int dp = __ldg(&dst[ep]);
            int cp = (t & 1) * 64;
            pf_l2(g_tsrc + (size_t)sp * 128 + cp);
            pf_l2(g_tdst + (size_t)dp * 128 + cp);
        }

        float acc[4][4][4];
        mm_one(sbase + SM_A, sbase + SM_BHI, warp, lane, acc);

        // -------- fragment epilogue: per-warp, no barrier needed --------
#pragma unroll
        for (int mt = 0; mt < 4; ++mt) {
#pragma unroll
            for (int rs = 0; rs < 2; ++rs) {
                int r = warpm * 64 + mt * 16 + q + rs * 8;
                int e = e0 + r;
                int s  = __ldg(&src[e]);
                int dd = __ldg(&dst[e]);
                const __half2* tsp = (const __half2*)(g_tsrc + (size_t)s * 128);
                const __half2* tdp = (const __half2*)(g_tdst + (size_t)dd * 128);
                float f[8];
#pragma unroll
                for (int nt = 0; nt < 4; ++nt) {
                    int ci = (warpn * 32 + nt * 8 + 2 * tid) >> 1;
                    float2 ts = __half22float2(__ldg(tsp + ci));
                    float2 td = __half22float2(__ldg(tdp + ci));
                    float v0 = acc[mt][nt][rs * 2]     + ts.x + td.x;
                    float v1 = acc[mt][nt][rs * 2 + 1] + ts.y + td.y;
                    v0 = (v0 > 0.f) ? v0 : 0.01f * v0;
                    v1 = (v1 > 0.f) ? v1 : 0.01f * v1;
                    f[nt * 2]     = v0 + bv[nt * 2];
                    f[nt * 2 + 1] = v1 + bv[nt * 2 + 1];
                }
                // logits for this warp's 2 heads (quad-reduce over tid)
                float l0 = f[0] * wsv[0] + f[1] * wsv[1] + f[2] * wsv[2] + f[3] * wsv[3];
                float l1 = f[4] * wsv[0] + f[5] * wsv[1] + f[6] * wsv[2] + f[7] * wsv[3];
                l0 += __shfl_xor_sync(0xffffffffu, l0, 1);
                l0 += __shfl_xor_sync(0xffffffffu, l0, 2);
                l1 += __shfl_xor_sync(0xffffffffu, l1, 1);
                l1 += __shfl_xor_sync(0xffffffffu, l1, 2);
                if (tid == 0) {
                    float nrm = __ldg(&norm[e]);
                    float ex0 = __expf(l0), ex1 = __expf(l1);
                    *(float2*)&g_a[(size_t)e * NHEAD + 2 * warpn] =
                        make_float2(ex0 * nrm, ex1 * nrm);
                    atomicAdd(&g_den[(size_t)dd * NHEAD + 2 * warpn],     ex0);
                    atomicAdd(&g_den[(size_t)dd * NHEAD + 2 * warpn + 1], ex1);
                }
                // head-sum partials into shared pd (spread-address ATOMS)
                float* pdr = pd_s + r * 16;
                atomicAdd(&pdr[2 * tid],         f[0] + f[4]);
                atomicAdd(&pdr[2 * tid + 1],     f[1] + f[5]);
                atomicAdd(&pdr[8 + 2 * tid],     f[2] + f[6]);
                atomicAdd(&pdr[8 + 2 * tid + 1], f[3] + f[7]);
            }
        }
        __syncthreads();   // pd complete; all A reads done

        // overlap: stage next tile || out2 write (+rezero pd by its reader)
        int nxt = tile + gridDim.x;
        if (nxt < ntiles)
            load_tile_stream(smc, SM_A, efeats, nxt * 128, t);
        if (t < 128) {
            float pdv[16];
#pragma unroll
            for (int j = 0; j < 4; ++j) {
                float4 v = ((float4*)(pd_s + t * 16))[j];
                pdv[j * 4] = v.x; pdv[j * 4 + 1] = v.y;
                pdv[j * 4 + 2] = v.z; pdv[j * 4 + 3] = v.w;
                ((float4*)(pd_s + t * 16))[j] = make_float4(0.f, 0.f, 0.f, 0.f);
            }
            stg_stream8(out2 + (size_t)(e0 + t) * DEF, pdv);
            stg_stream8(out2 + (size_t)(e0 + t) * DEF + 8, pdv + 8);
        }
        __syncthreads();   // A(t+1) staged; pd consumed+zeroed
    }
}

// ---------------- message passing (coalesced + shuffle reduce) ----------------
__global__ void k_msg(const int* __restrict__ src, const int* __restrict__ dst,
                      float* __restrict__ out1) {
    int gid = blockIdx.x * blockDim.x + threadIdx.x;
    int lane = gid & 31;
    int e = (gid >> 5) * 2 + (lane >> 4);
    if (e >= EE) return;
    int t16 = lane & 15;
    int h = t16 >> 1;
    int s  = __ldg(&src[e]);
    int dd = __ldg(&dst[e]);
    float w = __fdividef(__ldg(&g_a[(size_t)e * NHEAD + h]),
                         __ldg(&g_den[(size_t)dd * NHEAD + h]));
    uint4 hv = __ldg((const uint4*)(g_hnode + (size_t)s * 128) + t16);
    uint32_t hw[4] = {hv.x, hv.y, hv.z, hv.w};
    float p[8];
#pragma unroll
    for (int j = 0; j < 4; ++j) {
        float2 f = h2f2(hw[j]);
        p[2 * j]     = w * f.x;
        p[2 * j + 1] = w * f.y;
    }
#pragma unroll
    for (int m = 2; m <= 8; m <<= 1)
#pragma unroll
        for (int j = 0; j < 8; ++j)
            p[j] += __shfl_xor_sync(0xffffffffu, p[j], m);
    if ((lane & 14) == 0) {
        int dbase = (t16 & 1) * 8;
#pragma unroll
        for (int j = 0; j < 8; ++j)
            atomicAdd(&out1[(size_t)dd * DNF + dbase + j], p[j]);
    }
}

// ---------------- launch ------------------------------------------------------
extern "C" void kernel_launch(void* const* d_in, const int* in_sizes, int n_in,
                              void* d_out, int out_size) {
    const float* nfeats  = (const float*)d_in[0];
    const float* efeats  = (const float*)d_in[1];
    const float* norm    = (const float*)d_in[2];
    const int*   src     = (const int*)d_in[3];
    const int*   dst     = (const int*)d_in[4];
    const float* W_ni    = (const float*)d_in[5];
    const float* W_nj    = (const float*)d_in[6];
    const float* W_fij   = (const float*)d_in[7];
    const float* W_edges = (const float*)d_in[8];
    const float* W_attn  = (const float*)d_in[9];
    const float* bias    = (const float*)d_in[10];
    const float* W_node  = (const float*)d_in[11];
    const float* b_node  = (const float*)d_in[12];

    float* out1 = (float*)d_out;
    float* out2 = out1 + (size_t)NN * DNF;

    cudaFuncSetAttribute(k_node_mma, cudaFuncAttributeMaxDynamicSharedMemorySize, SMN_TOTAL);
    cudaFuncSetAttribute(k_edge_mma, cudaFuncAttributeMaxDynamicSharedMemorySize, SM_TOTAL);

    k_init<<<3125, 256>>>(out1);
    k_wb<<<dim3(128, 4), 128>>>(W_edges, W_ni, W_nj, W_fij, W_node, W_attn);
    k_node_mma<<<148, 256, SMN_TOTAL>>>(nfeats, b_node);
    k_edge_mma<<<296, 256, SM_TOTAL>>>(efeats, src, dst, norm, bias, out2);
    k_msg<<<(EE / 2) * 32 / 256, 256>>>(src, dst, out1);
}

// round 15
// speedup vs baseline: 1.0917x; 1.0917x over previous
#include <cuda_runtime.h>
#include <cuda_fp16.h>
#include <cstring>
#include <cstdint>

#define NN 50000
#define EE 400000
#define NHEAD 8
#define DEF 16
#define DNF 16

// ---------------- device global scratch ------------------------------------
__device__ float g_wsum[DEF];
// B operands as fp16 [n][k], row stride 136 (slot 0:tsrc 1:edge 2:tdst 3:hnode)
__device__ __half g_Bh[4 * 128 * 136];
__device__ __half g_tsrc[NN * 128];
__device__ __half g_tdst[NN * 128];
__device__ __half g_hnode[NN * 128];
__device__ float g_a[EE * NHEAD];    // exp(logit) * norm
__device__ float g_den[NN * NHEAD];  // sum of raw exp(logit)

// ---------------- smem layouts (bytes) ---------------------------------------
#define RSTRIDE 272                 // 136 fp16 per row
#define AB_BYTES (128 * RSTRIDE)    // 34816

// edge kernel: bias/ws | A | B | fbuf(fp16) -- A and fbuf DISJOINT
#define SM_BIAS 0
#define SM_WS   512
#define SM_A    1024
#define SM_BHI  (SM_A + AB_BYTES)       // 35840
#define SM_FB   (SM_BHI + AB_BYTES)     // 70656
#define SM_TOTAL (SM_FB + AB_BYTES)     // 105472  (2 CTAs/SM)

// fused node kernel layout
#define SMN_BIAS 0
#define SMN_AHI  1024
#define SMN_B0   (SMN_AHI + AB_BYTES)           // 35840
#define SMN_TOTAL (SMN_B0 + 3 * AB_BYTES)       // 140288

// ---------------- helpers ------------------------------------------------------
__device__ __forceinline__ uint32_t smem_u32(const void* p) {
    uint32_t a;
    asm("{ .reg .u64 t; cvta.to.shared.u64 t, %1; cvt.u32.u64 %0, t; }" : "=r"(a) : "l"(p));
    return a;
}
__device__ __forceinline__ float2 h2f2(uint32_t u) {
    __half2 h;
    memcpy(&h, &u, 4);
    return __half22float2(h);
}
// 256-bit streaming load (this toolchain requires v8.b32 for L2::evict_first)
__device__ __forceinline__ void ldg_stream8(const float* p, float4& v0, float4& v1) {
    uint32_t r0, r1, r2, r3, r4, r5, r6, r7;
    asm volatile("ld.global.nc.L2::evict_first.v8.b32 {%0,%1,%2,%3,%4,%5,%6,%7}, [%8];"
                 : "=r"(r0), "=r"(r1), "=r"(r2), "=r"(r3),
                   "=r"(r4), "=r"(r5), "=r"(r6), "=r"(r7) : "l"(p));
    v0.x = __uint_as_float(r0); v0.y = __uint_as_float(r1);
    v0.z = __uint_as_float(r2); v0.w = __uint_as_float(r3);
    v1.x = __uint_as_float(r4); v1.y = __uint_as_float(r5);
    v1.z = __uint_as_float(r6); v1.w = __uint_as_float(r7);
}
__device__ __forceinline__ void stg_stream8(float* p, const float* v) {
    asm volatile("st.global.L2::evict_first.v8.b32 [%0], {%1,%2,%3,%4,%5,%6,%7,%8};"
                 :: "l"(p),
                    "r"(__float_as_uint(v[0])), "r"(__float_as_uint(v[1])),
                    "r"(__float_as_uint(v[2])), "r"(__float_as_uint(v[3])),
                    "r"(__float_as_uint(v[4])), "r"(__float_as_uint(v[5])),
                    "r"(__float_as_uint(v[6])), "r"(__float_as_uint(v[7])));
}
__device__ __forceinline__ void pf_l2(const void* p) {
    asm volatile("prefetch.global.L2 [%0];" :: "l"(p));
}

// ---------------- small kernels ----------------------------------------------
__global__ void k_init(float* __restrict__ out1) {
    int i = blockIdx.x * blockDim.x + threadIdx.x;
    if (i < NN * NHEAD) g_den[i] = 0.f;
    if (i < NN * DNF)   out1[i] = 0.f;
}

// fused: combined weights -> fp16 B operands directly
__global__ void k_wb(const float* __restrict__ W_edges,
                     const float* __restrict__ W_ni,
                     const float* __restrict__ W_nj,
                     const float* __restrict__ W_fij,
                     const float* __restrict__ W_node,
                     const float* __restrict__ W_attn) {
    int k = blockIdx.x, c = threadIdx.x, m = blockIdx.y;
    float acc = 0.f;
    if (m == 0) {
        for (int j = 0; j < 128; ++j) acc += W_edges[c * 384 + j] * W_ni[j * 128 + k];
    } else if (m == 1) {
        for (int j = 0; j < 128; ++j) acc += W_edges[c * 384 + 128 + j] * W_fij[j * 128 + k];
    } else if (m == 2) {
        for (int j = 0; j < 128; ++j) acc += W_edges[c * 384 + 256 + j] * W_nj[j * 128 + k];
    } else {
        acc = W_node[c * 128 + k];
        if (k == 0 && c < DEF) {
            float s = 0.f;
            for (int h = 0; h < NHEAD; ++h) s += W_attn[h * DEF + c];
            g_wsum[c] = s;
        }
    }
    g_Bh[m * 128 * 136 + c * 136 + k] = __float2half_rn(acc);
}

// ---------------- fp32 -> fp16 tile stage -------------------------------------
__device__ __forceinline__ uint4 cvt8(const float4 v0, const float4 v1) {
    unsigned hu[4];
    __half2 h0 = __floats2half2_rn(v0.x, v0.y);
    __half2 h1 = __floats2half2_rn(v0.z, v0.w);
    __half2 h2 = __floats2half2_rn(v1.x, v1.y);
    __half2 h3 = __floats2half2_rn(v1.z, v1.w);
    memcpy(&hu[0], &h0, 4);
    memcpy(&hu[1], &h1, 4);
    memcpy(&hu[2], &h2, 4);
    memcpy(&hu[3], &h3, 4);
    return make_uint4(hu[0], hu[1], hu[2], hu[3]);
}

// node variant: normal loads (nfeats re-used across 3 mats in-kernel)
__device__ __forceinline__ void load_tile(char* smc, int ahioff,
                                          const float* __restrict__ srcp,
                                          int base, int limit, int t) {
#pragma unroll
    for (int j = 0; j < 8; ++j) {
        int i = t + j * 256;
        int row = i >> 4, col = (i & 15) * 8;
        int gr = base + row;
        float4 v0, v1;
        if (gr < limit) {
            v0 = __ldg((const float4*)(srcp + (size_t)gr * 128 + col));
            v1 = __ldg((const float4*)(srcp + (size_t)gr * 128 + col + 4));
        } else {
            v0 = make_float4(0.f, 0.f, 0.f, 0.f); v1 = v0;
        }
        *(uint4*)(smc + ahioff + row * RSTRIDE + col * 2) = cvt8(v0, v1);
    }
}

// edge variant: 256-bit streaming evict_first loads (protect gather tables in L2)
__device__ __forceinline__ void load_tile_stream(char* smc, int ahioff,
                                                 const float* __restrict__ srcp,
                                                 int base, int t) {
#pragma unroll
    for (int j = 0; j < 8; ++j) {
        int i = t + j * 256;
        int row = i >> 4, col = (i & 15) * 8;
        int gr = base + row;
        float4 v0, v1;
        ldg_stream8(srcp + (size_t)gr * 128 + col, v0, v1);
        *(uint4*)(smc + ahioff + row * RSTRIDE + col * 2) = cvt8(v0, v1);
    }
}

// ---------------- mma core (ldmatrix + single fp16 pass) -----------------------
__device__ __forceinline__ void mma16816(float (&d)[4], const uint32_t (&a)[4],
                                         uint32_t b0, uint32_t b1) {
    asm("mma.sync.aligned.m16n8k16.row.col.f32.f16.f16.f32 "
        "{%0,%1,%2,%3}, {%4,%5,%6,%7}, {%8,%9}, {%0,%1,%2,%3};"
        : "+f"(d[0]), "+f"(d[1]), "+f"(d[2]), "+f"(d[3])
        : "r"(a[0]), "r"(a[1]), "r"(a[2]), "r"(a[3]), "r"(b0), "r"(b1));
}

__device__ __forceinline__ void ldmat4(uint32_t (&r)[4], uint32_t addr) {
    asm volatile("ldmatrix.sync.aligned.m8n8.x4.shared.b16 {%0,%1,%2,%3}, [%4];"
                 : "=r"(r[0]), "=r"(r[1]), "=r"(r[2]), "=r"(r[3]) : "r"(addr));
}

// block tile 128x128, warp tile 64x32
__device__ __forceinline__ void mm_one(uint32_t aBase, uint32_t bBase,
                                       int warp, int lane, float (&acc)[4][4][4]) {
    int warpm = warp & 1, warpn = warp >> 1;
    uint32_t a_addr = aBase + (uint32_t)((warpm * 64 + (lane & 15)) * RSTRIDE + ((lane >> 4) << 4));
    uint32_t b_addr = bBase + (uint32_t)((warpn * 32 + (lane & 7) + ((lane >> 4) << 3)) * RSTRIDE
                                         + (((lane >> 3) & 1) << 4));

#pragma unroll
    for (int mt = 0; mt < 4; ++mt)
#pragma unroll
        for (int nt = 0; nt < 4; ++nt)
#pragma unroll
            for (int j = 0; j < 4; ++j) acc[mt][nt][j] = 0.f;

#pragma unroll
    for (int k0 = 0; k0 < 8; ++k0) {
        uint32_t ko = k0 * 32;
        uint32_t ahi[4][4], bhi[2][4];
#pragma unroll
        for (int mt = 0; mt < 4; ++mt)
            ldmat4(ahi[mt], a_addr + mt * 16 * RSTRIDE + ko);
#pragma unroll
        for (int g = 0; g < 2; ++g)
            ldmat4(bhi[g], b_addr + g * 16 * RSTRIDE + ko);
#pragma unroll
        for (int mt = 0; mt < 4; ++mt)
#pragma unroll
            for (int nt = 0; nt < 4; ++nt)
                mma16816(acc[mt][nt], ahi[mt],
                         bhi[nt >> 1][(nt & 1) * 2], bhi[nt >> 1][(nt & 1) * 2 + 1]);
    }
}

// fp16 accumulator staging (fbuf fits A-sized buffer)
__device__ __forceinline__ void dump_acc16(char* smc, int warp, int lane,
                                           const float (&acc)[4][4][4]) {
    int warpm = warp & 1, warpn = warp >> 1;
    int q = lane >> 2, tid = lane & 3;
    __half* fb = (__half*)(smc + SM_FB);
#pragma unroll
    for (int mt = 0; mt < 4; ++mt) {
        int r = warpm * 64 + mt * 16 + q;
#pragma unroll
        for (int nt = 0; nt < 4; ++nt) {
            int c = warpn * 32 + nt * 8 + 2 * tid;
            *(__half2*)&fb[r * 136 + c]       = __floats2half2_rn(acc[mt][nt][0], acc[mt][nt][1]);
            *(__half2*)&fb[(r + 8) * 136 + c] = __floats2half2_rn(acc[mt][nt][2], acc[mt][nt][3]);
        }
    }
}

// ---------------- fused node GEMMs: t_src / t_dst / h_node --------------------
__global__ void __launch_bounds__(256, 1)
k_node_mma(const float* __restrict__ nfeats, const float* __restrict__ b_node) {
    extern __shared__ char smc[];
    uint32_t sbase = smem_u32(smc);
    int t = threadIdx.x, warp = t >> 5, lane = t & 31;
    int warpm = warp & 1, warpn = warp >> 1;
    int q = lane >> 2, tid = lane & 3;

    // stage the 3 B operands (slots 0: tsrc, 2: tdst, 3: hnode)
    for (int i = t; i < 2176; i += 256) {
        ((uint4*)(smc + SMN_B0))[i]                = ((const uint4*)(g_Bh + 0 * 128 * 136))[i];
        ((uint4*)(smc + SMN_B0 + AB_BYTES))[i]     = ((const uint4*)(g_Bh + 2 * 128 * 136))[i];
        ((uint4*)(smc + SMN_B0 + 2 * AB_BYTES))[i] = ((const uint4*)(g_Bh + 3 * 128 * 136))[i];
    }
    float* bias_s = (float*)(smc + SMN_BIAS);
    for (int i = t; i < 128; i += 256) bias_s[i] = __ldg(&b_node[i]);

    const int ntiles = (NN + 127) / 128;   // 391
    for (int tile = blockIdx.x; tile < ntiles; tile += gridDim.x) {
        int n0 = tile * 128;
        load_tile(smc, SMN_AHI, nfeats, n0, NN, t);
        __syncthreads();
#pragma unroll 1
        for (int mat = 0; mat < 3; ++mat) {
            __half* OUT = (mat == 0) ? g_tsrc : (mat == 1 ? g_tdst : g_hnode);
            float acc[4][4][4];
            mm_one(sbase + SMN_AHI, sbase + SMN_B0 + mat * AB_BYTES, warp, lane, acc);
            // direct fragment -> fp16 gmem store
#pragma unroll
            for (int mt = 0; mt < 4; ++mt) {
                int rr = warpm * 64 + mt * 16 + q;
#pragma unroll
                for (int nt = 0; nt < 4; ++nt) {
                    int cc = warpn * 32 + nt * 8 + 2 * tid;
                    float b0 = 0.f, b1 = 0.f;
                    if (mat == 2) { b0 = bias_s[cc]; b1 = bias_s[cc + 1]; }
                    int n1 = n0 + rr, n2 = n1 + 8;
                    if (n1 < NN)
                        *(__half2*)(OUT + (size_t)n1 * 128 + cc) =
                            __floats2half2_rn(acc[mt][nt][0] + b0, acc[mt][nt][1] + b1);
                    if (n2 < NN)
                        *(__half2*)(OUT + (size_t)n2 * 128 + cc) =
                            __floats2half2_rn(acc[mt][nt][2] + b0, acc[mt][nt][3] + b1);
                }
            }
        }
        __syncthreads();   // all reads of A done before next load_tile
    }
}

// ---------------- fused edge kernel (pipelined, 2 barriers/tile) ---------------
__device__ __forceinline__ void edge_epilogue(char* smc, int e0, int t,
                                              const int* __restrict__ src,
                                              const int* __restrict__ dst,
                                              const float* __restrict__ norm,
                                              float* __restrict__ out2) {
    const float* bias_s = (const float*)(smc + SM_BIAS);
    const float* ws_s   = (const float*)(smc + SM_WS);
    int e = e0 + (t >> 1);
    int half = t & 1;
    int c0 = half * 64, h0 = half * 4;
    int s  = __ldg(&src[e]);
    int dd = __ldg(&dst[e]);
    float nrm = __ldg(&norm[e]);
    const uint4* frow = (const uint4*)(smc + SM_FB + (t >> 1) * RSTRIDE + c0 * 2);
    const uint4* tsp = (const uint4*)(g_tsrc + (size_t)s * 128 + c0);
    const uint4* tdp = (const uint4*)(g_tdst + (size_t)dd * 128 + c0);

    float pd[16];
#pragma unroll
    for (int d = 0; d < 16; ++d) pd[d] = 0.f;
    float ex[4], exn[4];
#pragma unroll
    for (int hl = 0; hl < 4; ++hl) {
        uint4 fv0 = frow[hl * 2],     fv1 = frow[hl * 2 + 1];
        uint4 sa0 = __ldg(tsp + hl * 2), sa1 = __ldg(tsp + hl * 2 + 1);
        uint4 da0 = __ldg(tdp + hl * 2), da1 = __ldg(tdp + hl * 2 + 1);
        uint32_t fw[8] = {fv0.x, fv0.y, fv0.z, fv0.w, fv1.x, fv1.y, fv1.z, fv1.w};
        uint32_t sw[8] = {sa0.x, sa0.y, sa0.z, sa0.w, sa1.x, sa1.y, sa1.z, sa1.w};
        uint32_t dw[8] = {da0.x, da0.y, da0.z, da0.w, da1.x, da1.y, da1.z, da1.w};
        float lgv = 0.f;
#pragma unroll
        for (int j = 0; j < 4; ++j) {
            float2 f01 = h2f2(fw[j * 2]), f23 = h2f2(fw[j * 2 + 1]);
            float2 s01 = h2f2(sw[j * 2]), s23 = h2f2(sw[j * 2 + 1]);
            float2 d01 = h2f2(dw[j * 2]), d23 = h2f2(dw[j * 2 + 1]);
            int cb = c0 + hl * 16 + j * 4;
            float v0 = f01.x + s01.x + d01.x;
            float v1 = f01.y + s01.y + d01.y;
            float v2 = f23.x + s23.x + d23.x;
            float v3 = f23.y + s23.y + d23.y;
            v0 = (v0 > 0.f) ? v0 : 0.01f * v0;
            v1 = (v1 > 0.f) ? v1 : 0.01f * v1;
            v2 = (v2 > 0.f) ? v2 : 0.01f * v2;
            v3 = (v3 > 0.f) ? v3 : 0.01f * v3;
            v0 += bias_s[cb];
            v1 += bias_s[cb + 1];
            v2 += bias_s[cb + 2];
            v3 += bias_s[cb + 3];
            pd[j * 4]     += v0;
            pd[j * 4 + 1] += v1;
            pd[j * 4 + 2] += v2;
            pd[j * 4 + 3] += v3;
            lgv += v0 * ws_s[j * 4] + v1 * ws_s[j * 4 + 1]
                 + v2 * ws_s[j * 4 + 2] + v3 * ws_s[j * 4 + 3];
        }
        ex[hl]  = __expf(lgv);
        exn[hl] = ex[hl] * nrm;
    }
#pragma unroll
    for (int d = 0; d < 16; ++d) pd[d] += __shfl_xor_sync(0xffffffffu, pd[d], 1);
    if (!half) {
        stg_stream8(out2 + (size_t)e * DEF, pd);
        stg_stream8(out2 + (size_t)e * DEF + 8, pd + 8);
    }
    ((float4*)g_a)[(size_t)e * 2 + half] = make_float4(exn[0], exn[1], exn[2], exn[3]);
#pragma unroll
    for (int hl = 0; hl < 4; ++hl)
        atomicAdd(&g_den[(size_t)dd * NHEAD + h0 + hl], ex[hl]);
}

__global__ void __launch_bounds__(256, 2)
k_edge_mma(const float* __restrict__ efeats, const int* __restrict__ src,
           const int* __restrict__ dst, const float* __restrict__ norm,
           const float* __restrict__ bias, float* __restrict__ out2) {
    extern __shared__ char smc[];
    uint32_t sbase = smem_u32(smc);
    int t = threadIdx.x, warp = t >> 5, lane = t & 31;

    const uint4* bh = (const uint4*)(g_Bh + 1 * 128 * 136);
    for (int i = t; i < 2176; i += 256)
        ((uint4*)(smc + SM_BHI))[i] = bh[i];
    float* bias_s = (float*)(smc + SM_BIAS);
    float* ws_s   = (float*)(smc + SM_WS);
    for (int i = t; i < 128; i += 256) bias_s[i] = __ldg(&bias[i]);
    if (t < DEF) ws_s[t] = g_wsum[t];

    const int ntiles = EE / 128;   // 3125 exact
    int tile = blockIdx.x;
    // prologue: stage first tile (grid 296 << 3125, always valid)
    load_tile_stream(smc, SM_A, efeats, tile * 128, t);
    __syncthreads();

    for (; tile < ntiles; tile += gridDim.x) {
        int e0 = tile * 128;
        // L2 prefetch two strides ahead (stage of tile+stride is this iteration)
        int nxt2 = tile + 2 * (int)gridDim.x;
        if (nxt2 < ntiles) {
            const char* nb = (const char*)(efeats + (size_t)nxt2 * 128 * 128);
            pf_l2(nb + t * 256);
            pf_l2(nb + t * 256 + 128);
        }
        // gather-row L2 prefetch BEFORE mma: lead time ~ full MMA phase
        {
            int ep = e0 + (t >> 1);
            int sp = __ldg(&src[ep]);
            int dp = __ldg(&dst[ep]);
            int cp = (t & 1) * 64;
            pf_l2(g_tsrc + (size_t)sp * 128 + cp);
            pf_l2(g_tdst + (size_t)dp * 128 + cp);
        }
        float acc[4][4][4];
        mm_one(sbase + SM_A, sbase + SM_BHI, warp, lane, acc);
        // NOTE: no barrier here — mma->dump is a same-warp register dependency;
        // cross-warp A/fbuf hazards are covered by the barrier below.
        dump_acc16(smc, warp, lane, acc);
        __syncthreads();          // all A reads + all fbuf writes complete

        // overlap region: stage next tile (A dead) || epilogue this tile (fbuf)
        int nxt = tile + gridDim.x;
        if (nxt < ntiles)
            load_tile_stream(smc, SM_A, efeats, nxt * 128, t);
        edge_epilogue(smc, e0, t, src, dst, norm, out2);
        __syncthreads();          // stage complete + fbuf reads done
    }
}

// ---------------- message passing (coalesced + shuffle reduce) ----------------
__global__ void k_msg(const int* __restrict__ src, const int* __restrict__ dst,
                      float* __restrict__ out1) {
    int gid = blockIdx.x * blockDim.x + threadIdx.x;
    int lane = gid & 31;
    int e = (gid >> 5) * 2 + (lane >> 4);
    if (e >= EE) return;
    int t16 = lane & 15;
    int h = t16 >> 1;
    int s  = __ldg(&src[e]);
    int dd = __ldg(&dst[e]);
    float w = __fdividef(__ldg(&g_a[(size_t)e * NHEAD + h]),
                         __ldg(&g_den[(size_t)dd * NHEAD + h]));
    uint4 hv = __ldg((const uint4*)(g_hnode + (size_t)s * 128) + t16);
    uint32_t hw[4] = {hv.x, hv.y, hv.z, hv.w};
    float p[8];
#pragma unroll
    for (int j = 0; j < 4; ++j) {
        float2 f = h2f2(hw[j]);
        p[2 * j]     = w * f.x;
        p[2 * j + 1] = w * f.y;
    }
#pragma unroll
    for (int m = 2; m <= 8; m <<= 1)
#pragma unroll
        for (int j = 0; j < 8; ++j)
            p[j] += __shfl_xor_sync(0xffffffffu, p[j], m);
    if ((lane & 14) == 0) {
        int dbase = (t16 & 1) * 8;
#pragma unroll
        for (int j = 0; j < 8; ++j)
            atomicAdd(&out1[(size_t)dd * DNF + dbase + j], p[j]);
    }
}

// ---------------- launch ------------------------------------------------------
extern "C" void kernel_launch(void* const* d_in, const int* in_sizes, int n_in,
                              void* d_out, int out_size) {
    const float* nfeats  = (const float*)d_in[0];
    const float* efeats  = (const float*)d_in[1];
    const float* norm    = (const float*)d_in[2];
    const int*   src     = (const int*)d_in[3];
    const int*   dst     = (const int*)d_in[4];
    const float* W_ni    = (const float*)d_in[5];
    const float* W_nj    = (const float*)d_in[6];
    const float* W_fij   = (const float*)d_in[7];
    const float* W_edges = (const float*)d_in[8];
    const float* W_attn  = (const float*)d_in[9];
    const float* bias    = (const float*)d_in[10];
    const float* W_node  = (const float*)d_in[11];
    const float* b_node  = (const float*)d_in[12];

    float* out1 = (float*)d_out;
    float* out2 = out1 + (size_t)NN * DNF;

    cudaFuncSetAttribute(k_node_mma, cudaFuncAttributeMaxDynamicSharedMemorySize, SMN_TOTAL);
    cudaFuncSetAttribute(k_edge_mma, cudaFuncAttributeMaxDynamicSharedMemorySize, SM_TOTAL);

    k_init<<<3125, 256>>>(out1);
    k_wb<<<dim3(128, 4), 128>>>(W_edges, W_ni, W_nj, W_fij, W_node, W_attn);
    k_node_mma<<<148, 256, SMN_TOTAL>>>(nfeats, b_node);
    k_edge_mma<<<296, 256, SM_TOTAL>>>(efeats, src, dst, norm, bias, out2);
    k_msg<<<(EE / 2) * 32 / 256, 256>>>(src, dst, out1);
}

// round 16
// speedup vs baseline: 1.1072x; 1.0142x over previous
#include <cuda_runtime.h>
#include <cuda_fp16.h>
#include <cstring>
#include <cstdint>

#define NN 50000
#define EE 400000
#define NHEAD 8
#define DEF 16
#define DNF 16

// ---------------- device global scratch ------------------------------------
__device__ float g_wsum[DEF];
// B operands as fp16 [n][k], row stride 136 (slot 0:tsrc 1:edge 2:tdst 3:hnode)
__device__ __half g_Bh[4 * 128 * 136];
__device__ __half g_tsrc[NN * 128];
__device__ __half g_tdst[NN * 128];
__device__ __half g_hnode[NN * 128];
__device__ float g_a[EE * NHEAD];    // exp(logit) * norm
__device__ float g_den[NN * NHEAD];  // sum of raw exp(logit)

// ---------------- smem layouts (bytes) ---------------------------------------
#define RSTRIDE 272                 // 136 fp16 per row
#define AB_BYTES (128 * RSTRIDE)    // 34816

// edge kernel: bias/ws | A | B | fbuf(fp16) -- A and fbuf DISJOINT
#define SM_BIAS 0
#define SM_WS   512
#define SM_A    1024
#define SM_BHI  (SM_A + AB_BYTES)       // 35840
#define SM_FB   (SM_BHI + AB_BYTES)     // 70656
#define SM_TOTAL (SM_FB + AB_BYTES)     // 105472  (2 CTAs/SM)

// fused node kernel layout
#define SMN_BIAS 0
#define SMN_AHI  1024
#define SMN_B0   (SMN_AHI + AB_BYTES)           // 35840
#define SMN_TOTAL (SMN_B0 + 3 * AB_BYTES)       // 140288

// ---------------- helpers ------------------------------------------------------
__device__ __forceinline__ uint32_t smem_u32(const void* p) {
    uint32_t a;
    asm("{ .reg .u64 t; cvta.to.shared.u64 t, %1; cvt.u32.u64 %0, t; }" : "=r"(a) : "l"(p));
    return a;
}
__device__ __forceinline__ float2 h2f2(uint32_t u) {
    __half2 h;
    memcpy(&h, &u, 4);
    return __half22float2(h);
}
// 256-bit streaming load (this toolchain requires v8.b32 for L2::evict_first)
__device__ __forceinline__ void ldg_stream8(const float* p, float4& v0, float4& v1) {
    uint32_t r0, r1, r2, r3, r4, r5, r6, r7;
    asm volatile("ld.global.nc.L2::evict_first.v8.b32 {%0,%1,%2,%3,%4,%5,%6,%7}, [%8];"
                 : "=r"(r0), "=r"(r1), "=r"(r2), "=r"(r3),
                   "=r"(r4), "=r"(r5), "=r"(r6), "=r"(r7) : "l"(p));
    v0.x = __uint_as_float(r0); v0.y = __uint_as_float(r1);
    v0.z = __uint_as_float(r2); v0.w = __uint_as_float(r3);
    v1.x = __uint_as_float(r4); v1.y = __uint_as_float(r5);
    v1.z = __uint_as_float(r6); v1.w = __uint_as_float(r7);
}
__device__ __forceinline__ void stg_stream8(float* p, const float* v) {
    asm volatile("st.global.L2::evict_first.v8.b32 [%0], {%1,%2,%3,%4,%5,%6,%7,%8};"
                 :: "l"(p),
                    "r"(__float_as_uint(v[0])), "r"(__float_as_uint(v[1])),
                    "r"(__float_as_uint(v[2])), "r"(__float_as_uint(v[3])),
                    "r"(__float_as_uint(v[4])), "r"(__float_as_uint(v[5])),
                    "r"(__float_as_uint(v[6])), "r"(__float_as_uint(v[7])));
}
__device__ __forceinline__ void pf_l2(const void* p) {
    asm volatile("prefetch.global.L2 [%0];" :: "l"(p));
}
// vector atomic add, no return (sm_90+ PTX)
__device__ __forceinline__ void red_add4(float* p, float a, float b, float c, float d) {
    asm volatile("red.global.add.v4.f32 [%0], {%1,%2,%3,%4};"
                 :: "l"(p), "f"(a), "f"(b), "f"(c), "f"(d) : "memory");
}

// ---------------- small kernels ----------------------------------------------
__global__ void k_init(float* __restrict__ out1) {
    int i = blockIdx.x * blockDim.x + threadIdx.x;
    if (i < NN * NHEAD) g_den[i] = 0.f;
    if (i < NN * DNF)   out1[i] = 0.f;
}

// fused: combined weights -> fp16 B operands directly
__global__ void k_wb(const float* __restrict__ W_edges,
                     const float* __restrict__ W_ni,
                     const float* __restrict__ W_nj,
                     const float* __restrict__ W_fij,
                     const float* __restrict__ W_node,
                     const float* __restrict__ W_attn) {
    int k = blockIdx.x, c = threadIdx.x, m = blockIdx.y;
    float acc = 0.f;
    if (m == 0) {
        for (int j = 0; j < 128; ++j) acc += W_edges[c * 384 + j] * W_ni[j * 128 + k];
    } else if (m == 1) {
        for (int j = 0; j < 128; ++j) acc += W_edges[c * 384 + 128 + j] * W_fij[j * 128 + k];
    } else if (m == 2) {
        for (int j = 0; j < 128; ++j) acc += W_edges[c * 384 + 256 + j] * W_nj[j * 128 + k];
    } else {
        acc = W_node[c * 128 + k];
        if (k == 0 && c < DEF) {
            float s = 0.f;
            for (int h = 0; h < NHEAD; ++h) s += W_attn[h * DEF + c];
            g_wsum[c] = s;
        }
    }
    g_Bh[m * 128 * 136 + c * 136 + k] = __float2half_rn(acc);
}

// ---------------- fp32 -> fp16 tile stage -------------------------------------
__device__ __forceinline__ uint4 cvt8(const float4 v0, const float4 v1) {
    unsigned hu[4];
    __half2 h0 = __floats2half2_rn(v0.x, v0.y);
    __half2 h1 = __floats2half2_rn(v0.z, v0.w);
    __half2 h2 = __floats2half2_rn(v1.x, v1.y);
    __half2 h3 = __floats2half2_rn(v1.z, v1.w);
    memcpy(&hu[0], &h0, 4);
    memcpy(&hu[1], &h1, 4);
    memcpy(&hu[2], &h2, 4);
    memcpy(&hu[3], &h3, 4);
    return make_uint4(hu[0], hu[1], hu[2], hu[3]);
}

// node variant (512 threads): normal loads
__device__ __forceinline__ void load_tile512(char* smc, int ahioff,
                                             const float* __restrict__ srcp,
                                             int base, int limit, int t) {
#pragma unroll
    for (int j = 0; j < 4; ++j) {
        int i = t + j * 512;
        int row = i >> 4, col = (i & 15) * 8;
        int gr = base + row;
        float4 v0, v1;
        if (gr < limit) {
            v0 = __ldg((const float4*)(srcp + (size_t)gr * 128 + col));
            v1 = __ldg((const float4*)(srcp + (size_t)gr * 128 + col + 4));
        } else {
            v0 = make_float4(0.f, 0.f, 0.f, 0.f); v1 = v0;
        }
        *(uint4*)(smc + ahioff + row * RSTRIDE + col * 2) = cvt8(v0, v1);
    }
}

// edge variant (256 threads): 256-bit streaming evict_first loads
__device__ __forceinline__ void load_tile_stream(char* smc, int ahioff,
                                                 const float* __restrict__ srcp,
                                                 int base, int t) {
#pragma unroll
    for (int j = 0; j < 8; ++j) {
        int i = t + j * 256;
        int row = i >> 4, col = (i & 15) * 8;
        int gr = base + row;
        float4 v0, v1;
        ldg_stream8(srcp + (size_t)gr * 128 + col, v0, v1);
        *(uint4*)(smc + ahioff + row * RSTRIDE + col * 2) = cvt8(v0, v1);
    }
}

// ---------------- mma core (ldmatrix + single fp16 pass) -----------------------
__device__ __forceinline__ void mma16816(float (&d)[4], const uint32_t (&a)[4],
                                         uint32_t b0, uint32_t b1) {
    asm("mma.sync.aligned.m16n8k16.row.col.f32.f16.f16.f32 "
        "{%0,%1,%2,%3}, {%4,%5,%6,%7}, {%8,%9}, {%0,%1,%2,%3};"
        : "+f"(d[0]), "+f"(d[1]), "+f"(d[2]), "+f"(d[3])
        : "r"(a[0]), "r"(a[1]), "r"(a[2]), "r"(a[3]), "r"(b0), "r"(b1));
}

__device__ __forceinline__ void ldmat4(uint32_t (&r)[4], uint32_t addr) {
    asm volatile("ldmatrix.sync.aligned.m8n8.x4.shared.b16 {%0,%1,%2,%3}, [%4];"
                 : "=r"(r[0]), "=r"(r[1]), "=r"(r[2]), "=r"(r[3]) : "r"(addr));
}

// edge: block tile 128x128, 8 warps, warp tile 64x32
__device__ __forceinline__ void mm_one(uint32_t aBase, uint32_t bBase,
                                       int warp, int lane, float (&acc)[4][4][4]) {
    int warpm = warp & 1, warpn = warp >> 1;
    uint32_t a_addr = aBase + (uint32_t)((warpm * 64 + (lane & 15)) * RSTRIDE + ((lane >> 4) << 4));
    uint32_t b_addr = bBase + (uint32_t)((warpn * 32 + (lane & 7) + ((lane >> 4) << 3)) * RSTRIDE
                                         + (((lane >> 3) & 1) << 4));

#pragma unroll
    for (int mt = 0; mt < 4; ++mt)
#pragma unroll
        for (int nt = 0; nt < 4; ++nt)
#pragma unroll
            for (int j = 0; j < 4; ++j) acc[mt][nt][j] = 0.f;

#pragma unroll
    for (int k0 = 0; k0 < 8; ++k0) {
        uint32_t ko = k0 * 32;
        uint32_t ahi[4][4], bhi[2][4];
#pragma unroll
        for (int mt = 0; mt < 4; ++mt)
            ldmat4(ahi[mt], a_addr + mt * 16 * RSTRIDE + ko);
#pragma unroll
        for (int g = 0; g < 2; ++g)
            ldmat4(bhi[g], b_addr + g * 16 * RSTRIDE + ko);
#pragma unroll
        for (int mt = 0; mt < 4; ++mt)
#pragma unroll
            for (int nt = 0; nt < 4; ++nt)
                mma16816(acc[mt][nt], ahi[mt],
                         bhi[nt >> 1][(nt & 1) * 2], bhi[nt >> 1][(nt & 1) * 2 + 1]);
    }
}

// node: block tile 128x128, 16 warps, warp tile 32x32
__device__ __forceinline__ void mm_one32(uint32_t aBase, uint32_t bBase,
                                         int warp, int lane, float (&acc)[2][4][4]) {
    int warpm = warp & 3, warpn = warp >> 2;
    uint32_t a_addr = aBase + (uint32_t)((warpm * 32 + (lane & 15)) * RSTRIDE + ((lane >> 4) << 4));
    uint32_t b_addr = bBase + (uint32_t)((warpn * 32 + (lane & 7) + ((lane >> 4) << 3)) * RSTRIDE
                                         + (((lane >> 3) & 1) << 4));

#pragma unroll
    for (int mt = 0; mt < 2; ++mt)
#pragma unroll
        for (int nt = 0; nt < 4; ++nt)
#pragma unroll
            for (int j = 0; j < 4; ++j) acc[mt][nt][j] = 0.f;

#pragma unroll
    for (int k0 = 0; k0 < 8; ++k0) {
        uint32_t ko = k0 * 32;
        uint32_t ahi[2][4], bhi[2][4];
#pragma unroll
        for (int mt = 0; mt < 2; ++mt)
            ldmat4(ahi[mt], a_addr + mt * 16 * RSTRIDE + ko);
#pragma unroll
        for (int g = 0; g < 2; ++g)
            ldmat4(bhi[g], b_addr + g * 16 * RSTRIDE + ko);
#pragma unroll
        for (int mt = 0; mt < 2; ++mt)
#pragma unroll
            for (int nt = 0; nt < 4; ++nt)
                mma16816(acc[mt][nt], ahi[mt],
                         bhi[nt >> 1][(nt & 1) * 2], bhi[nt >> 1][(nt & 1) * 2 + 1]);
    }
}

// fp16 accumulator staging (edge)
__device__ __forceinline__ void dump_acc16(char* smc, int warp, int lane,
                                           const float (&acc)[4][4][4]) {
    int warpm = warp & 1, warpn = warp >> 1;
    int q = lane >> 2, tid = lane & 3;
    __half* fb = (__half*)(smc + SM_FB);
#pragma unroll
    for (int mt = 0; mt < 4; ++mt) {
        int r = warpm * 64 + mt * 16 + q;
#pragma unroll
        for (int nt = 0; nt < 4; ++nt) {
            int c = warpn * 32 + nt * 8 + 2 * tid;
            *(__half2*)&fb[r * 136 + c]       = __floats2half2_rn(acc[mt][nt][0], acc[mt][nt][1]);
            *(__half2*)&fb[(r + 8) * 136 + c] = __floats2half2_rn(acc[mt][nt][2], acc[mt][nt][3]);
        }
    }
}

// ---------------- fused node GEMMs: t_src / t_dst / h_node --------------------
// 512 threads, 16 warps, warp tile 32x32, 1 CTA/SM
__global__ void __launch_bounds__(512, 1)
k_node_mma(const float* __restrict__ nfeats, const float* __restrict__ b_node) {
    extern __shared__ char smc[];
    uint32_t sbase = smem_u32(smc);
    int t = threadIdx.x, warp = t >> 5, lane = t & 31;
    int warpm = warp & 3, warpn = warp >> 2;
    int q = lane >> 2, tid = lane & 3;

    // stage the 3 B operands (slots 0: tsrc, 2: tdst, 3: hnode)
    for (int i = t; i < 2176; i += 512) {
        ((uint4*)(smc + SMN_B0))[i]                = ((const uint4*)(g_Bh + 0 * 128 * 136))[i];
        ((uint4*)(smc + SMN_B0 + AB_BYTES))[i]     = ((const uint4*)(g_Bh + 2 * 128 * 136))[i];
        ((uint4*)(smc + SMN_B0 + 2 * AB_BYTES))[i] = ((const uint4*)(g_Bh + 3 * 128 * 136))[i];
    }
    float* bias_s = (float*)(smc + SMN_BIAS);
    for (int i = t; i < 128; i += 512) bias_s[i] = __ldg(&b_node[i]);

    const int ntiles = (NN + 127) / 128;   // 391
    for (int tile = blockIdx.x; tile < ntiles; tile += gridDim.x) {
        int n0 = tile * 128;
        load_tile512(smc, SMN_AHI, nfeats, n0, NN, t);
        __syncthreads();
#pragma unroll 1
        for (int mat = 0; mat < 3; ++mat) {
            __half* OUT = (mat == 0) ? g_tsrc : (mat == 1 ? g_tdst : g_hnode);
            float acc[2][4][4];
            mm_one32(sbase + SMN_AHI, sbase + SMN_B0 + mat * AB_BYTES, warp, lane, acc);
            // direct fragment -> fp16 gmem store
#pragma unroll
            for (int mt = 0; mt < 2; ++mt) {
                int rr = warpm * 32 + mt * 16 + q;
#pragma unroll
                for (int nt = 0; nt < 4; ++nt) {
                    int cc = warpn * 32 + nt * 8 + 2 * tid;
                    float b0 = 0.f, b1 = 0.f;
                    if (mat == 2) { b0 = bias_s[cc]; b1 = bias_s[cc + 1]; }
                    int n1 = n0 + rr, n2 = n1 + 8;
                    if (n1 < NN)
                        *(__half2*)(OUT + (size_t)n1 * 128 + cc) =
                            __floats2half2_rn(acc[mt][nt][0] + b0, acc[mt][nt][1] + b1);
                    if (n2 < NN)
                        *(__half2*)(OUT + (size_t)n2 * 128 + cc) =
                            __floats2half2_rn(acc[mt][nt][2] + b0, acc[mt][nt][3] + b1);
                }
            }
        }
        __syncthreads();   // all reads of A done before next load_tile
    }
}

// ---------------- fused edge kernel (pipelined, 2 barriers/tile) ---------------
__device__ __forceinline__ void edge_epilogue(char* smc, int e0, int t,
                                              const int* __restrict__ src,
                                              const int* __restrict__ dst,
                                              const float* __restrict__ norm,
                                              float* __restrict__ out2) {
    const float* bias_s = (const float*)(smc + SM_BIAS);
    const float* ws_s   = (const float*)(smc + SM_WS);
    int e = e0 + (t >> 1);
    int half = t & 1;
    int c0 = half * 64, h0 = half * 4;
    int s  = __ldg(&src[e]);
    int dd = __ldg(&dst[e]);
    float nrm = __ldg(&norm[e]);
    const uint4* frow = (const uint4*)(smc + SM_FB + (t >> 1) * RSTRIDE + c0 * 2);
    const uint4* tsp = (const uint4*)(g_tsrc + (size_t)s * 128 + c0);
    const uint4* tdp = (const uint4*)(g_tdst + (size_t)dd * 128 + c0);

    float pd[16];
#pragma unroll
    for (int d = 0; d < 16; ++d) pd[d] = 0.f;
    float ex[4], exn[4];
#pragma unroll
    for (int hl = 0; hl < 4; ++hl) {
        uint4 fv0 = frow[hl * 2],     fv1 = frow[hl * 2 + 1];
        uint4 sa0 = __ldg(tsp + hl * 2), sa1 = __ldg(tsp + hl * 2 + 1);
        uint4 da0 = __ldg(tdp + hl * 2), da1 = __ldg(tdp + hl * 2 + 1);
        uint32_t fw[8] = {fv0.x, fv0.y, fv0.z, fv0.w, fv1.x, fv1.y, fv1.z, fv1.w};
        uint32_t sw[8] = {sa0.x, sa0.y, sa0.z, sa0.w, sa1.x, sa1.y, sa1.z, sa1.w};
        uint32_t dw[8] = {da0.x, da0.y, da0.z, da0.w, da1.x, da1.y, da1.z, da1.w};
        float lgv = 0.f;
#pragma unroll
        for (int j = 0; j < 4; ++j) {
            float2 f01 = h2f2(fw[j * 2]), f23 = h2f2(fw[j * 2 + 1]);
            float2 s01 = h2f2(sw[j * 2]), s23 = h2f2(sw[j * 2 + 1]);
            float2 d01 = h2f2(dw[j * 2]), d23 = h2f2(dw[j * 2 + 1]);
            int cb = c0 + hl * 16 + j * 4;
            float v0 = f01.x + s01.x + d01.x;
            float v1 = f01.y + s01.y + d01.y;
            float v2 = f23.x + s23.x + d23.x;
            float v3 = f23.y + s23.y + d23.y;
            v0 = (v0 > 0.f) ? v0 : 0.01f * v0;
            v1 = (v1 > 0.f) ? v1 : 0.01f * v1;
            v2 = (v2 > 0.f) ? v2 : 0.01f * v2;
            v3 = (v3 > 0.f) ? v3 : 0.01f * v3;
            v0 += bias_s[cb];
            v1 += bias_s[cb + 1];
            v2 += bias_s[cb + 2];
            v3 += bias_s[cb + 3];
            pd[j * 4]     += v0;
            pd[j * 4 + 1] += v1;
            pd[j * 4 + 2] += v2;
            pd[j * 4 + 3] += v3;
            lgv += v0 * ws_s[j * 4] + v1 * ws_s[j * 4 + 1]
                 + v2 * ws_s[j * 4 + 2] + v3 * ws_s[j * 4 + 3];
        }
        ex[hl]  = __expf(lgv);
        exn[hl] = ex[hl] * nrm;
    }
#pragma unroll
    for (int d = 0; d < 16; ++d) pd[d] += __shfl_xor_sync(0xffffffffu, pd[d], 1);
    if (!half) {
        stg_stream8(out2 + (size_t)e * DEF, pd);
        stg_stream8(out2 + (size_t)e * DEF + 8, pd + 8);
    }
    ((float4*)g_a)[(size_t)e * 2 + half] = make_float4(exn[0], exn[1], exn[2], exn[3]);
#pragma unroll
    for (int hl = 0; hl < 4; ++hl)
        atomicAdd(&g_den[(size_t)dd * NHEAD + h0 + hl], ex[hl]);
}

__global__ void __launch_bounds__(256, 2)
k_edge_mma(const float* __restrict__ efeats, const int* __restrict__ src,
           const int* __restrict__ dst, const float* __restrict__ norm,
           const float* __restrict__ bias, float* __restrict__ out2) {
    extern __shared__ char smc[];
    uint32_t sbase = smem_u32(smc);
    int t = threadIdx.x, warp = t >> 5, lane = t & 31;

    const uint4* bh = (const uint4*)(g_Bh + 1 * 128 * 136);
    for (int i = t; i < 2176; i += 256)
        ((uint4*)(smc + SM_BHI))[i] = bh[i];
    float* bias_s = (float*)(smc + SM_BIAS);
    float* ws_s   = (float*)(smc + SM_WS);
    for (int i = t; i < 128; i += 256) bias_s[i] = __ldg(&bias[i]);
    if (t < DEF) ws_s[t] = g_wsum[t];

    const int ntiles = EE / 128;   // 3125 exact
    int tile = blockIdx.x;
    // prologue: stage first tile (grid 296 << 3125, always valid)
    load_tile_stream(smc, SM_A, efeats, tile * 128, t);
    __syncthreads();

    for (; tile < ntiles; tile += gridDim.x) {
        int e0 = tile * 128;
        // L2 prefetch two strides ahead (stage of tile+stride is this iteration)
        int nxt2 = tile + 2 * (int)gridDim.x;
        if (nxt2 < ntiles) {
            const char* nb = (const char*)(efeats + (size_t)nxt2 * 128 * 128);
            pf_l2(nb + t * 256);
            pf_l2(nb + t * 256 + 128);
        }
        // gather-row L2 prefetch BEFORE mma: lead time ~ full MMA phase
        {
            int ep = e0 + (t >> 1);
            int sp = __ldg(&src[ep]);
            int dp = __ldg(&dst[ep]);
            int cp = (t & 1) * 64;
            pf_l2(g_tsrc + (size_t)sp * 128 + cp);
            pf_l2(g_tdst + (size_t)dp * 128 + cp);
        }
        float acc[4][4][4];
        mm_one(sbase + SM_A, sbase + SM_BHI, warp, lane, acc);
        // NOTE: no barrier here — mma->dump is a same-warp register dependency;
        // cross-warp A/fbuf hazards are covered by the barrier below.
        dump_acc16(smc, warp, lane, acc);
        __syncthreads();          // all A reads + all fbuf writes complete

        // overlap region: stage next tile (A dead) || epilogue this tile (fbuf)
        int nxt = tile + gridDim.x;
        if (nxt < ntiles)
            load_tile_stream(smc, SM_A, efeats, nxt * 128, t);
        edge_epilogue(smc, e0, t, src, dst, norm, out2);
        __syncthreads();          // stage complete + fbuf reads done
    }
}

// ---------------- message passing (coalesced + shuffle + vector red) ----------
__global__ void k_msg(const int* __restrict__ src, const int* __restrict__ dst,
                      float* __restrict__ out1) {
    int gid = blockIdx.x * blockDim.x + threadIdx.x;
    int lane = gid & 31;
    int e = (gid >> 5) * 2 + (lane >> 4);
    if (e >= EE) return;
    int t16 = lane & 15;
    int h = t16 >> 1;
    int s  = __ldg(&src[e]);
    int dd = __ldg(&dst[e]);
    float w = __fdividef(__ldg(&g_a[(size_t)e * NHEAD + h]),
                         __ldg(&g_den[(size_t)dd * NHEAD + h]));
    uint4 hv = __ldg((const uint4*)(g_hnode + (size_t)s * 128) + t16);
    uint32_t hw[4] = {hv.x, hv.y, hv.z, hv.w};
    float p[8];
#pragma unroll
    for (int j = 0; j < 4; ++j) {
        float2 f = h2f2(hw[j]);
        p[2 * j]     = w * f.x;
        p[2 * j + 1] = w * f.y;
    }
#pragma unroll
    for (int m = 2; m <= 8; m <<= 1)
#pragma unroll
        for (int j = 0; j < 8; ++j)
            p[j] += __shfl_xor_sync(0xffffffffu, p[j], m);
    if ((lane & 14) == 0) {
        int dbase = (t16 & 1) * 8;
        float* op = out1 + (size_t)dd * DNF + dbase;
        red_add4(op,     p[0], p[1], p[2], p[3]);
        red_add4(op + 4, p[4], p[5], p[6], p[7]);
    }
}

// ---------------- launch ------------------------------------------------------
extern "C" void kernel_launch(void* const* d_in, const int* in_sizes, int n_in,
                              void* d_out, int out_size) {
    const float* nfeats  = (const float*)d_in[0];
    const float* efeats  = (const float*)d_in[1];
    const float* norm    = (const float*)d_in[2];
    const int*   src     = (const int*)d_in[3];
    const int*   dst     = (const int*)d_in[4];
    const float* W_ni    = (const float*)d_in[5];
    const float* W_nj    = (const float*)d_in[6];
    const float* W_fij   = (const float*)d_in[7];
    const float* W_edges = (const float*)d_in[8];
    const float* W_attn  = (const float*)d_in[9];
    const float* bias    = (const float*)d_in[10];
    const float* W_node  = (const float*)d_in[11];
    const float* b_node  = (const float*)d_in[12];

    float* out1 = (float*)d_out;
    float* out2 = out1 + (size_t)NN * DNF;

    cudaFuncSetAttribute(k_node_mma, cudaFuncAttributeMaxDynamicSharedMemorySize, SMN_TOTAL);
    cudaFuncSetAttribute(k_edge_mma, cudaFuncAttributeMaxDynamicSharedMemorySize, SM_TOTAL);

    k_init<<<3125, 256>>>(out1);
    k_wb<<<dim3(128, 4), 128>>>(W_edges, W_ni, W_nj, W_fij, W_node, W_attn);
    k_node_mma<<<148, 512, SMN_TOTAL>>>(nfeats, b_node);
    k_edge_mma<<<296, 256, SM_TOTAL>>>(efeats, src, dst, norm, bias, out2);
    k_msg<<<(EE / 2) * 32 / 256, 256>>>(src, dst, out1);
}

// round 17
// speedup vs baseline: 1.1624x; 1.0499x over previous
#include <cuda_runtime.h>
#include <cuda_fp16.h>
#include <cstring>
#include <cstdint>

#define NN 50000
#define EE 400000
#define NHEAD 8
#define DEF 16
#define DNF 16

// ---------------- device global scratch ------------------------------------
__device__ float g_wsum[DEF];
// B operands as fp16 [n][k], row stride 136 (slot 0:tsrc 1:edge 2:tdst 3:hnode)
__device__ __half g_Bh[4 * 128 * 136];
__device__ __half g_tsrc[NN * 128];
__device__ __half g_tdst[NN * 128];
__device__ __half g_hnode[NN * 128];
__device__ float g_a[EE * NHEAD];    // exp(logit) * norm
__device__ float g_den[NN * NHEAD];  // sum of raw exp(logit)

// ---------------- smem layouts (bytes) ---------------------------------------
#define RSTRIDE 272                 // 136 fp16 per row
#define AB_BYTES (128 * RSTRIDE)    // 34816

// edge kernel: bias/ws | A | B | fbuf(fp16) -- A and fbuf DISJOINT
#define SM_BIAS 0
#define SM_WS   512
#define SM_A    1024
#define SM_BHI  (SM_A + AB_BYTES)       // 35840
#define SM_FB   (SM_BHI + AB_BYTES)     // 70656
#define SM_TOTAL (SM_FB + AB_BYTES)     // 105472  (2 CTAs/SM)

// fused node kernel layout
#define SMN_BIAS 0
#define SMN_AHI  1024
#define SMN_B0   (SMN_AHI + AB_BYTES)           // 35840
#define SMN_TOTAL (SMN_B0 + 3 * AB_BYTES)       // 140288

// ---------------- helpers ------------------------------------------------------
__device__ __forceinline__ uint32_t smem_u32(const void* p) {
    uint32_t a;
    asm("{ .reg .u64 t; cvta.to.shared.u64 t, %1; cvt.u32.u64 %0, t; }" : "=r"(a) : "l"(p));
    return a;
}
__device__ __forceinline__ float2 h2f2(uint32_t u) {
    __half2 h;
    memcpy(&h, &u, 4);
    return __half22float2(h);
}
// 256-bit streaming load (this toolchain requires v8.b32 for L2::evict_first)
__device__ __forceinline__ void ldg_stream8(const float* p, float4& v0, float4& v1) {
    uint32_t r0, r1, r2, r3, r4, r5, r6, r7;
    asm volatile("ld.global.nc.L2::evict_first.v8.b32 {%0,%1,%2,%3,%4,%5,%6,%7}, [%8];"
                 : "=r"(r0), "=r"(r1), "=r"(r2), "=r"(r3),
                   "=r"(r4), "=r"(r5), "=r"(r6), "=r"(r7) : "l"(p));
    v0.x = __uint_as_float(r0); v0.y = __uint_as_float(r1);
    v0.z = __uint_as_float(r2); v0.w = __uint_as_float(r3);
    v1.x = __uint_as_float(r4); v1.y = __uint_as_float(r5);
    v1.z = __uint_as_float(r6); v1.w = __uint_as_float(r7);
}
__device__ __forceinline__ void stg_stream8(float* p, const float* v) {
    asm volatile("st.global.L2::evict_first.v8.b32 [%0], {%1,%2,%3,%4,%5,%6,%7,%8};"
                 :: "l"(p),
                    "r"(__float_as_uint(v[0])), "r"(__float_as_uint(v[1])),
                    "r"(__float_as_uint(v[2])), "r"(__float_as_uint(v[3])),
                    "r"(__float_as_uint(v[4])), "r"(__float_as_uint(v[5])),
                    "r"(__float_as_uint(v[6])), "r"(__float_as_uint(v[7])));
}
__device__ __forceinline__ void pf_l2(const void* p) {
    asm volatile("prefetch.global.L2 [%0];" :: "l"(p));
}
// vector atomic add, no return (sm_90+ PTX)
__device__ __forceinline__ void red_add4(float* p, float a, float b, float c, float d) {
    asm volatile("red.global.add.v4.f32 [%0], {%1,%2,%3,%4};"
                 :: "l"(p), "f"(a), "f"(b), "f"(c), "f"(d) : "memory");
}

// ---------------- fused weights + init kernel ---------------------------------
__global__ void k_wb(const float* __restrict__ W_edges,
                     const float* __restrict__ W_ni,
                     const float* __restrict__ W_nj,
                     const float* __restrict__ W_fij,
                     const float* __restrict__ W_node,
                     const float* __restrict__ W_attn,
                     float* __restrict__ out1) {
    int k = blockIdx.x, c = threadIdx.x, m = blockIdx.y;
    // zeroing duty (merged former k_init): 65536 threads grid-stride
    int gid = (m * 128 + k) * 128 + c;
    for (int i = gid; i < NN * NHEAD; i += 65536) g_den[i] = 0.f;
    for (int i = gid; i < NN * DNF; i += 65536) out1[i] = 0.f;

    float acc = 0.f;
    if (m == 0) {
        for (int j = 0; j < 128; ++j) acc += W_edges[c * 384 + j] * W_ni[j * 128 + k];
    } else if (m == 1) {
        for (int j = 0; j < 128; ++j) acc += W_edges[c * 384 + 128 + j] * W_fij[j * 128 + k];
    } else if (m == 2) {
        for (int j = 0; j < 128; ++j) acc += W_edges[c * 384 + 256 + j] * W_nj[j * 128 + k];
    } else {
        acc = W_node[c * 128 + k];
        if (k == 0 && c < DEF) {
            float s = 0.f;
            for (int h = 0; h < NHEAD; ++h) s += W_attn[h * DEF + c];
            g_wsum[c] = s;
        }
    }
    g_Bh[m * 128 * 136 + c * 136 + k] = __float2half_rn(acc);
}

// ---------------- fp32 -> fp16 tile stage -------------------------------------
__device__ __forceinline__ uint4 cvt8(const float4 v0, const float4 v1) {
    unsigned hu[4];
    __half2 h0 = __floats2half2_rn(v0.x, v0.y);
    __half2 h1 = __floats2half2_rn(v0.z, v0.w);
    __half2 h2 = __floats2half2_rn(v1.x, v1.y);
    __half2 h3 = __floats2half2_rn(v1.z, v1.w);
    memcpy(&hu[0], &h0, 4);
    memcpy(&hu[1], &h1, 4);
    memcpy(&hu[2], &h2, 4);
    memcpy(&hu[3], &h3, 4);
    return make_uint4(hu[0], hu[1], hu[2], hu[3]);
}

// node (512 threads): prefetch into registers
__device__ __forceinline__ void pf_tile512(float4 (&pf)[8],
                                           const float* __restrict__ srcp,
                                           int base, int limit, int t) {
#pragma unroll
    for (int j = 0; j < 4; ++j) {
        int i = t + j * 512;
        int row = i >> 4, col = (i & 15) * 8;
        int gr = base + row;
        if (gr < limit) {
            pf[2 * j]     = __ldg((const float4*)(srcp + (size_t)gr * 128 + col));
            pf[2 * j + 1] = __ldg((const float4*)(srcp + (size_t)gr * 128 + col + 4));
        } else {
            pf[2 * j] = make_float4(0.f, 0.f, 0.f, 0.f);
            pf[2 * j + 1] = pf[2 * j];
        }
    }
}
__device__ __forceinline__ void sts_tile512(char* smc, int ahioff,
                                            const float4 (&pf)[8], int t) {
#pragma unroll
    for (int j = 0; j < 4; ++j) {
        int i = t + j * 512;
        int row = i >> 4, col = (i & 15) * 8;
        *(uint4*)(smc + ahioff + row * RSTRIDE + col * 2) = cvt8(pf[2 * j], pf[2 * j + 1]);
    }
}

// edge variant (256 threads): 256-bit streaming evict_first loads
__device__ __forceinline__ void load_tile_stream(char* smc, int ahioff,
                                                 const float* __restrict__ srcp,
                                                 int base, int t) {
#pragma unroll
    for (int j = 0; j < 8; ++j) {
        int i = t + j * 256;
        int row = i >> 4, col = (i & 15) * 8;
        int gr = base + row;
        float4 v0, v1;
        ldg_stream8(srcp + (size_t)gr * 128 + col, v0, v1);
        *(uint4*)(smc + ahioff + row * RSTRIDE + col * 2) = cvt8(v0, v1);
    }
}

// ---------------- mma core (ldmatrix + single fp16 pass) -----------------------
__device__ __forceinline__ void mma16816(float (&d)[4], const uint32_t (&a)[4],
                                         uint32_t b0, uint32_t b1) {
    asm("mma.sync.aligned.m16n8k16.row.col.f32.f16.f16.f32 "
        "{%0,%1,%2,%3}, {%4,%5,%6,%7}, {%8,%9}, {%0,%1,%2,%3};"
        : "+f"(d[0]), "+f"(d[1]), "+f"(d[2]), "+f"(d[3])
        : "r"(a[0]), "r"(a[1]), "r"(a[2]), "r"(a[3]), "r"(b0), "r"(b1));
}

__device__ __forceinline__ void ldmat4(uint32_t (&r)[4], uint32_t addr) {
    asm volatile("ldmatrix.sync.aligned.m8n8.x4.shared.b16 {%0,%1,%2,%3}, [%4];"
                 : "=r"(r[0]), "=r"(r[1]), "=r"(r[2]), "=r"(r[3]) : "r"(addr));
}

// edge: block tile 128x128, 8 warps, warp tile 64x32
__device__ __forceinline__ void mm_one(uint32_t aBase, uint32_t bBase,
                                       int warp, int lane, float (&acc)[4][4][4]) {
    int warpm = warp & 1, warpn = warp >> 1;
    uint32_t a_addr = aBase + (uint32_t)((warpm * 64 + (lane & 15)) * RSTRIDE + ((lane >> 4) << 4));
    uint32_t b_addr = bBase + (uint32_t)((warpn * 32 + (lane & 7) + ((lane >> 4) << 3)) * RSTRIDE
                                         + (((lane >> 3) & 1) << 4));

#pragma unroll
    for (int mt = 0; mt < 4; ++mt)
#pragma unroll
        for (int nt = 0; nt < 4; ++nt)
#pragma unroll
            for (int j = 0; j < 4; ++j) acc[mt][nt][j] = 0.f;

#pragma unroll
    for (int k0 = 0; k0 < 8; ++k0) {
        uint32_t ko = k0 * 32;
        uint32_t ahi[4][4], bhi[2][4];
#pragma unroll
        for (int mt = 0; mt < 4; ++mt)
            ldmat4(ahi[mt], a_addr + mt * 16 * RSTRIDE + ko);
#pragma unroll
        for (int g = 0; g < 2; ++g)
            ldmat4(bhi[g], b_addr + g * 16 * RSTRIDE + ko);
#pragma unroll
        for (int mt = 0; mt < 4; ++mt)
#pragma unroll
            for (int nt = 0; nt < 4; ++nt)
                mma16816(acc[mt][nt], ahi[mt],
                         bhi[nt >> 1][(nt & 1) * 2], bhi[nt >> 1][(nt & 1) * 2 + 1]);
    }
}

// node: block tile 128x128, 16 warps, warp tile 32x32
__device__ __forceinline__ void mm_one32(uint32_t aBase, uint32_t bBase,
                                         int warp, int lane, float (&acc)[2][4][4]) {
    int warpm = warp & 3, warpn = warp >> 2;
    uint32_t a_addr = aBase + (uint32_t)((warpm * 32 + (lane & 15)) * RSTRIDE + ((lane >> 4) << 4));
    uint32_t b_addr = bBase + (uint32_t)((warpn * 32 + (lane & 7) + ((lane >> 4) << 3)) * RSTRIDE
                                         + (((lane >> 3) & 1) << 4));

#pragma unroll
    for (int mt = 0; mt < 2; ++mt)
#pragma unroll
        for (int nt = 0; nt < 4; ++nt)
#pragma unroll
            for (int j = 0; j < 4; ++j) acc[mt][nt][j] = 0.f;

#pragma unroll
    for (int k0 = 0; k0 < 8; ++k0) {
        uint32_t ko = k0 * 32;
        uint32_t ahi[2][4], bhi[2][4];
#pragma unroll
        for (int mt = 0; mt < 2; ++mt)
            ldmat4(ahi[mt], a_addr + mt * 16 * RSTRIDE + ko);
#pragma unroll
        for (int g = 0; g < 2; ++g)
            ldmat4(bhi[g], b_addr + g * 16 * RSTRIDE + ko);
#pragma unroll
        for (int mt = 0; mt < 2; ++mt)
#pragma unroll
            for (int nt = 0; nt < 4; ++nt)
                mma16816(acc[mt][nt], ahi[mt],
                         bhi[nt >> 1][(nt & 1) * 2], bhi[nt >> 1][(nt & 1) * 2 + 1]);
    }
}

// fp16 accumulator staging (edge)
__device__ __forceinline__ void dump_acc16(char* smc, int warp, int lane,
                                           const float (&acc)[4][4][4]) {
    int warpm = warp & 1, warpn = warp >> 1;
    int q = lane >> 2, tid = lane & 3;
    __half* fb = (__half*)(smc + SM_FB);
#pragma unroll
    for (int mt = 0; mt < 4; ++mt) {
        int r = warpm * 64 + mt * 16 + q;
#pragma unroll
        for (int nt = 0; nt < 4; ++nt) {
            int c = warpn * 32 + nt * 8 + 2 * tid;
            *(__half2*)&fb[r * 136 + c]       = __floats2half2_rn(acc[mt][nt][0], acc[mt][nt][1]);
            *(__half2*)&fb[(r + 8) * 136 + c] = __floats2half2_rn(acc[mt][nt][2], acc[mt][nt][3]);
        }
    }
}

// ---------------- fused node GEMMs: t_src / t_dst / h_node --------------------
// 512 threads, 16 warps, warp tile 32x32, 1 CTA/SM, register prefetch pipeline
__global__ void __launch_bounds__(512, 1)
k_node_mma(const float* __restrict__ nfeats, const float* __restrict__ b_node) {
    extern __shared__ char smc[];
    uint32_t sbase = smem_u32(smc);
    int t = threadIdx.x, warp = t >> 5, lane = t & 31;
    int warpm = warp & 3, warpn = warp >> 2;
    int q = lane >> 2, tid = lane & 3;

    // stage the 3 B operands (slots 0: tsrc, 2: tdst, 3: hnode)
    for (int i = t; i < 2176; i += 512) {
        ((uint4*)(smc + SMN_B0))[i]                = ((const uint4*)(g_Bh + 0 * 128 * 136))[i];
        ((uint4*)(smc + SMN_B0 + AB_BYTES))[i]     = ((const uint4*)(g_Bh + 2 * 128 * 136))[i];
        ((uint4*)(smc + SMN_B0 + 2 * AB_BYTES))[i] = ((const uint4*)(g_Bh + 3 * 128 * 136))[i];
    }
    float* bias_s = (float*)(smc + SMN_BIAS);
    for (int i = t; i < 128; i += 512) bias_s[i] = __ldg(&b_node[i]);

    const int ntiles = (NN + 127) / 128;   // 391
    int tile = blockIdx.x;
    float4 pf[8];
    if (tile < ntiles) pf_tile512(pf, nfeats, tile * 128, NN, t);

    for (; tile < ntiles; tile += gridDim.x) {
        int n0 = tile * 128;
        __syncthreads();   // prev tile's A reads done (first iter: covers B stage too)
        sts_tile512(smc, SMN_AHI, pf, t);
        __syncthreads();   // A ready
        int nxt = tile + gridDim.x;
        if (nxt < ntiles) pf_tile512(pf, nfeats, nxt * 128, NN, t);  // hidden by MMAs
#pragma unroll 1
        for (int mat = 0; mat < 3; ++mat) {
            __half* OUT = (mat == 0) ? g_tsrc : (mat == 1 ? g_tdst : g_hnode);
            float acc[2][4][4];
            mm_one32(sbase + SMN_AHI, sbase + SMN_B0 + mat * AB_BYTES, warp, lane, acc);
            // direct fragment -> fp16 gmem store
#pragma unroll
            for (int mt = 0; mt < 2; ++mt) {
                int rr = warpm * 32 + mt * 16 + q;
#pragma unroll
                for (int nt = 0; nt < 4; ++nt) {
                    int cc = warpn * 32 + nt * 8 + 2 * tid;
                    float b0 = 0.f, b1 = 0.f;
                    if (mat == 2) { b0 = bias_s[cc]; b1 = bias_s[cc + 1]; }
                    int n1 = n0 + rr, n2 = n1 + 8;
                    if (n1 < NN)
                        *(__half2*)(OUT + (size_t)n1 * 128 + cc) =
                            __floats2half2_rn(acc[mt][nt][0] + b0, acc[mt][nt][1] + b1);
                    if (n2 < NN)
                        *(__half2*)(OUT + (size_t)n2 * 128 + cc) =
                            __floats2half2_rn(acc[mt][nt][2] + b0, acc[mt][nt][3] + b1);
                }
            }
        }
    }
}

// ---------------- fused edge kernel (pipelined, 2 barriers/tile) ---------------
__device__ __forceinline__ void edge_epilogue(char* smc, int e0, int t,
                                              const int* __restrict__ src,
                                              const int* __restrict__ dst,
                                              const float* __restrict__ norm,
                                              float* __restrict__ out2) {
    const float* bias_s = (const float*)(smc + SM_BIAS);
    const float* ws_s   = (const float*)(smc + SM_WS);
    int e = e0 + (t >> 1);
    int half = t & 1;
    int c0 = half * 64, h0 = half * 4;
    int s  = __ldg(&src[e]);
    int dd = __ldg(&dst[e]);
    float nrm = __ldg(&norm[e]);
    const uint4* frow = (const uint4*)(smc + SM_FB + (t >> 1) * RSTRIDE + c0 * 2);
    const uint4* tsp = (const uint4*)(g_tsrc + (size_t)s * 128 + c0);
    const uint4* tdp = (const uint4*)(g_tdst + (size_t)dd * 128 + c0);

    float pd[16];
#pragma unroll
    for (int d = 0; d < 16; ++d) pd[d] = 0.f;
    float ex[4], exn[4];
#pragma unroll
    for (int hl = 0; hl < 4; ++hl) {
        uint4 fv0 = frow[hl * 2],     fv1 = frow[hl * 2 + 1];
        uint4 sa0 = __ldg(tsp + hl * 2), sa1 = __ldg(tsp + hl * 2 + 1);
        uint4 da0 = __ldg(tdp + hl * 2), da1 = __ldg(tdp + hl * 2 + 1);
        uint32_t fw[8] = {fv0.x, fv0.y, fv0.z, fv0.w, fv1.x, fv1.y, fv1.z, fv1.w};
        uint32_t sw[8] = {sa0.x, sa0.y, sa0.z, sa0.w, sa1.x, sa1.y, sa1.z, sa1.w};
        uint32_t dw[8] = {da0.x, da0.y, da0.z, da0.w, da1.x, da1.y, da1.z, da1.w};
        float lgv = 0.f;
#pragma unroll
        for (int j = 0; j < 4; ++j) {
            float2 f01 = h2f2(fw[j * 2]), f23 = h2f2(fw[j * 2 + 1]);
            float2 s01 = h2f2(sw[j * 2]), s23 = h2f2(sw[j * 2 + 1]);
            float2 d01 = h2f2(dw[j * 2]), d23 = h2f2(dw[j * 2 + 1]);
            int cb = c0 + hl * 16 + j * 4;
            float v0 = f01.x + s01.x + d01.x;
            float v1 = f01.y + s01.y + d01.y;
            float v2 = f23.x + s23.x + d23.x;
            float v3 = f23.y + s23.y + d23.y;
            v0 = (v0 > 0.f) ? v0 : 0.01f * v0;
            v1 = (v1 > 0.f) ? v1 : 0.01f * v1;
            v2 = (v2 > 0.f) ? v2 : 0.01f * v2;
            v3 = (v3 > 0.f) ? v3 : 0.01f * v3;
            v0 += bias_s[cb];
            v1 += bias_s[cb + 1];
            v2 += bias_s[cb + 2];
            v3 += bias_s[cb + 3];
            pd[j * 4]     += v0;
            pd[j * 4 + 1] += v1;
            pd[j * 4 + 2] += v2;
            pd[j * 4 + 3] += v3;
            lgv += v0 * ws_s[j * 4] + v1 * ws_s[j * 4 + 1]
                 + v2 * ws_s[j * 4 + 2] + v3 * ws_s[j * 4 + 3];
        }
        ex[hl]  = __expf(lgv);
        exn[hl] = ex[hl] * nrm;
    }
#pragma unroll
    for (int d = 0; d < 16; ++d) pd[d] += __shfl_xor_sync(0xffffffffu, pd[d], 1);
    if (!half) {
        stg_stream8(out2 + (size_t)e * DEF, pd);
        stg_stream8(out2 + (size_t)e * DEF + 8, pd + 8);
    }
    ((float4*)g_a)[(size_t)e * 2 + half] = make_float4(exn[0], exn[1], exn[2], exn[3]);
    red_add4(&g_den[(size_t)dd * NHEAD + h0], ex[0], ex[1], ex[2], ex[3]);
}

__global__ void __launch_bounds__(256, 2)
k_edge_mma(const float* __restrict__ efeats, const int* __restrict__ src,
           const int* __restrict__ dst, const float* __restrict__ norm,
           const float* __restrict__ bias, float* __restrict__ out2) {
    extern __shared__ char smc[];
    uint32_t sbase = smem_u32(smc);
    int t = threadIdx.x, warp = t >> 5, lane = t & 31;

    const uint4* bh = (const uint4*)(g_Bh + 1 * 128 * 136);
    for (int i = t; i < 2176; i += 256)
        ((uint4*)(smc + SM_BHI))[i] = bh[i];
    float* bias_s = (float*)(smc + SM_BIAS);
    float* ws_s   = (float*)(smc + SM_WS);
    for (int i = t; i < 128; i += 256) bias_s[i] = __ldg(&bias[i]);
    if (t < DEF) ws_s[t] = g_wsum[t];

    const int ntiles = EE / 128;   // 3125 exact
    int tile = blockIdx.x;
    // prologue: stage first tile (grid 296 << 3125, always valid)
    load_tile_stream(smc, SM_A, efeats, tile * 128, t);
    __syncthreads();

    for (; tile < ntiles; tile += gridDim.x) {
        int e0 = tile * 128;
        // L2 prefetch two strides ahead (stage of tile+stride is this iteration)
        int nxt2 = tile + 2 * (int)gridDim.x;
        if (nxt2 < ntiles) {
            const char* nb = (const char*)(efeats + (size_t)nxt2 * 128 * 128);
            pf_l2(nb + t * 256);
            pf_l2(nb + t * 256 + 128);
        }
        // gather-row L2 prefetch BEFORE mma: lead time ~ full MMA phase
        {
            int ep = e0 + (t >> 1);
            int sp = __ldg(&src[ep]);
            int dp = __ldg(&dst[ep]);
            int cp = (t & 1) * 64;
            pf_l2(g_tsrc + (size_t)sp * 128 + cp);
            pf_l2(g_tdst + (size_t)dp * 128 + cp);
        }
        float acc[4][4][4];
        mm_one(sbase + SM_A, sbase + SM_BHI, warp, lane, acc);
        // no barrier: mma->dump is a same-warp register dependency
        dump_acc16(smc, warp, lane, acc);
        __syncthreads();          // all A reads + all fbuf writes complete

        // overlap region: stage next tile (A dead) || epilogue this tile (fbuf)
        int nxt = tile + gridDim.x;
        if (nxt < ntiles)
            load_tile_stream(smc, SM_A, efeats, nxt * 128, t);
        edge_epilogue(smc, e0, t, src, dst, norm, out2);
        __syncthreads();          // stage complete + fbuf reads done
    }
}

// ---------------- message passing (coalesced + shuffle + vector red) ----------
__global__ void k_msg(const int* __restrict__ src, const int* __restrict__ dst,
                      float* __restrict__ out1) {
    int gid = blockIdx.x * blockDim.x + threadIdx.x;
    int lane = gid & 31;
    int e = (gid >> 5) * 2 + (lane >> 4);
    if (e >= EE) return;
    int t16 = lane & 15;
    int h = t16 >> 1;
    int s  = __ldg(&src[e]);
    int dd = __ldg(&dst[e]);
    float w = __fdividef(__ldg(&g_a[(size_t)e * NHEAD + h]),
                         __ldg(&g_den[(size_t)dd * NHEAD + h]));
    uint4 hv = __ldg((const uint4*)(g_hnode + (size_t)s * 128) + t16);
    uint32_t hw[4] = {hv.x, hv.y, hv.z, hv.w};
    float p[8];
#pragma unroll
    for (int j = 0; j < 4; ++j) {
        float2 f = h2f2(hw[j]);
        p[2 * j]     = w * f.x;
        p[2 * j + 1] = w * f.y;
    }
#pragma unroll
    for (int m = 2; m <= 8; m <<= 1)
#pragma unroll
        for (int j = 0; j < 8; ++j)
            p[j] += __shfl_xor_sync(0xffffffffu, p[j], m);
    if ((lane & 14) == 0) {
        int dbase = (t16 & 1) * 8;
        float* op = out1 + (size_t)dd * DNF + dbase;
        red_add4(op,     p[0], p[1], p[2], p[3]);
        red_add4(op + 4, p[4], p[5], p[6], p[7]);
    }
}

// ---------------- launch ------------------------------------------------------
extern "C" void kernel_launch(void* const* d_in, const int* in_sizes, int n_in,
                              void* d_out, int out_size) {
    const float* nfeats  = (const float*)d_in[0];
    const float* efeats  = (const float*)d_in[1];
    const float* norm    = (const float*)d_in[2];
    const int*   src     = (const int*)d_in[3];
    const int*   dst     = (const int*)d_in[4];
    const float* W_ni    = (const float*)d_in[5];
    const float* W_nj    = (const float*)d_in[6];
    const float* W_fij   = (const float*)d_in[7];
    const float* W_edges = (const float*)d_in[8];
    const float* W_attn  = (const float*)d_in[9];
    const float* bias    = (const float*)d_in[10];
    const float* W_node  = (const float*)d_in[11];
    const float* b_node  = (const float*)d_in[12];

    float* out1 = (float*)d_out;
    float* out2 = out1 + (size_t)NN * DNF;

    cudaFuncSetAttribute(k_node_mma, cudaFuncAttributeMaxDynamicSharedMemorySize, SMN_TOTAL);
    cudaFuncSetAttribute(k_edge_mma, cudaFuncAttributeMaxDynamicSharedMemorySize, SM_TOTAL);

    k_wb<<<dim3(128, 4), 128>>>(W_edges, W_ni, W_nj, W_fij, W_node, W_attn, out1);
    k_node_mma<<<148, 512, SMN_TOTAL>>>(nfeats, b_node);
    k_edge_mma<<<296, 256, SM_TOTAL>>>(efeats, src, dst, norm, bias, out2);
    k_msg<<<(EE / 2) * 32 / 256, 256>>>(src, dst, out1);
}